// round 8
// baseline (speedup 1.0000x reference)
#include <cuda_runtime.h>
#include <math.h>

// Problem constants
#define B_  64
#define T_  10
#define D_  1024
#define E_  2048
#define M_  640            // B*T
#define SCALE_ 0.022097086912079612f   // 1/sqrt(2048)

typedef unsigned long long u64;

// ---------------------------------------------------------------------------
// Scratch (device globals — no allocation allowed)
// ---------------------------------------------------------------------------
__device__ __align__(16) float g_joint[M_ * E_];            // [B,T,E]
__device__ __align__(16) float g_keyT[2][B_ * D_ * 12];     // [br][b][d][t(pad12)]
__device__ __align__(16) float g_valT[2][B_ * D_ * 12];     // [br][b][d][t(pad12)]
__device__ __align__(16) float g_att[2][M_ * E_];           // relu(tanh(weighted)) [br][B,T,E]

__device__ __forceinline__ float tanh_fast(float x) {
    float y;
    asm("tanh.approx.f32 %0, %1;" : "=f"(y) : "f"(x));
    return y;
}
__device__ __forceinline__ u64 pack2(float lo, float hi) {
    u64 r; asm("mov.b64 %0, {%1, %2};" : "=l"(r) : "f"(lo), "f"(hi)); return r;
}
__device__ __forceinline__ void unpack2(u64 v, float& lo, float& hi) {
    asm("mov.b64 {%0, %1}, %2;" : "=f"(lo), "=f"(hi) : "l"(v));
}
__device__ __forceinline__ u64 fma2(u64 a, u64 b, u64 c) {
    u64 d; asm("fma.rn.f32x2 %0, %1, %2, %3;" : "=l"(d) : "l"(a), "l"(b), "l"(c)); return d;
}
__device__ __forceinline__ u64 mul2(u64 a, u64 b) {
    u64 d; asm("mul.rn.f32x2 %0, %1, %2;" : "=l"(d) : "l"(a), "l"(b)); return d;
}
__device__ __forceinline__ u64 add2(u64 a, u64 b) {
    u64 d; asm("add.rn.f32x2 %0, %1, %2;" : "=l"(d) : "l"(a), "l"(b)); return d;
}

// ---------------------------------------------------------------------------
// joint = concat(audio, video) @ Wq + bq        [640,2048] x [2048,2048]
// 64x128 tile, BK=16, 256 threads, 4x8 per thread. Register-prefetch
// software pipeline: tile t+1 LDGs issued before tile t compute.
// grid: (16, 10)
// ---------------------------------------------------------------------------
__global__ __launch_bounds__(256) void k_joint(const float* __restrict__ audio,
                                               const float* __restrict__ video,
                                               const float* __restrict__ Wq,
                                               const float* __restrict__ bq) {
    __shared__ __align__(16) u64   sA[64][17];
    __shared__ __align__(16) float sB[16][132];
    const int bm = blockIdx.y * 64, bn = blockIdx.x * 128;
    const int tid = threadIdx.x;
    const int tx = tid & 15, ty = tid >> 4;
    const int ar = tid >> 2, ac4 = (tid & 3) * 4;           // A-load coords
    const int br0 = tid >> 5, bc0 = (tid & 31) * 4;         // B-load coords (i=0)
    const int br1 = (tid + 256) >> 5, bc1 = bc0;            // B-load coords (i=1)

    float4 ra, rb0, rb1;
    {   // prefetch tile 0
        const float* src = audio;
        ra  = *(const float4*)&src[(size_t)(bm + ar) * D_ + ac4];
        rb0 = *(const float4*)&Wq[(size_t)(0 + br0) * E_ + bn + bc0];
        rb1 = *(const float4*)&Wq[(size_t)(0 + br1) * E_ + bn + bc1];
    }

    u64 acc[4][4] = {};
    for (int k0 = 0; k0 < E_; k0 += 16) {
        // store prefetched tile to smem
        sA[ar][ac4 + 0] = pack2(ra.x, ra.x);
        sA[ar][ac4 + 1] = pack2(ra.y, ra.y);
        sA[ar][ac4 + 2] = pack2(ra.z, ra.z);
        sA[ar][ac4 + 3] = pack2(ra.w, ra.w);
        *(float4*)&sB[br0][bc0] = rb0;
        *(float4*)&sB[br1][bc1] = rb1;
        __syncthreads();

        // prefetch tile t+1 (overlaps with compute below)
        int kn = k0 + 16;
        if (kn < E_) {
            const float* src = (kn < D_) ? audio : video;
            const int kb = (kn < D_) ? kn : (kn - D_);
            ra  = *(const float4*)&src[(size_t)(bm + ar) * D_ + kb + ac4];
            rb0 = *(const float4*)&Wq[(size_t)(kn + br0) * E_ + bn + bc0];
            rb1 = *(const float4*)&Wq[(size_t)(kn + br1) * E_ + bn + bc1];
        }

        #pragma unroll
        for (int k = 0; k < 16; k++) {
            ulonglong2 bp0 = *(const ulonglong2*)&sB[k][tx * 8];
            ulonglong2 bp1 = *(const ulonglong2*)&sB[k][tx * 8 + 4];
            #pragma unroll
            for (int i = 0; i < 4; i++) {
                u64 ap = sA[ty * 4 + i][k];
                acc[i][0] = fma2(ap, bp0.x, acc[i][0]);
                acc[i][1] = fma2(ap, bp0.y, acc[i][1]);
                acc[i][2] = fma2(ap, bp1.x, acc[i][2]);
                acc[i][3] = fma2(ap, bp1.y, acc[i][3]);
            }
        }
        __syncthreads();
    }
    float4 bias0 = *(const float4*)&bq[bn + tx * 8];
    float4 bias1 = *(const float4*)&bq[bn + tx * 8 + 4];
    #pragma unroll
    for (int i = 0; i < 4; i++) {
        float4 o0, o1;
        unpack2(acc[i][0], o0.x, o0.y);
        unpack2(acc[i][1], o0.z, o0.w);
        unpack2(acc[i][2], o1.x, o1.y);
        unpack2(acc[i][3], o1.z, o1.w);
        o0.x += bias0.x; o0.y += bias0.y; o0.z += bias0.z; o0.w += bias0.w;
        o1.x += bias1.x; o1.y += bias1.y; o1.z += bias1.z; o1.w += bias1.w;
        float* dst = &g_joint[(size_t)(bm + ty * 4 + i) * E_ + bn + tx * 8];
        *(float4*)dst = o0;
        *(float4*)(dst + 4) = o1;
    }
}

// ---------------------------------------------------------------------------
// key{1,2}[b,d,t] = sum_t' x[b,t',d] * Wk[t',t] + bk[t]
// grid: (256, 2)  block: 256
// ---------------------------------------------------------------------------
__global__ __launch_bounds__(256) void k_key(const float* __restrict__ audio,
                                             const float* __restrict__ video,
                                             const float* __restrict__ Wk1,
                                             const float* __restrict__ bk1,
                                             const float* __restrict__ Wk2,
                                             const float* __restrict__ bk2) {
    const int br = blockIdx.y;
    const float* x  = br ? video : audio;
    const float* Wk = br ? Wk2 : Wk1;
    const float* bk = br ? bk2 : bk1;

    __shared__ float w[100];
    __shared__ float bkv[10];
    if (threadIdx.x < 100) w[threadIdx.x] = Wk[threadIdx.x];
    if (threadIdx.x < 10)  bkv[threadIdx.x] = bk[threadIdx.x];
    __syncthreads();

    const int idx = blockIdx.x * 256 + threadIdx.x;
    const int b = idx >> 10, d = idx & 1023;

    float xr[10];
    #pragma unroll
    for (int t = 0; t < 10; t++) xr[t] = x[(b * T_ + t) * D_ + d];

    float* o = g_keyT[br] + (size_t)(b * D_ + d) * 12;
    #pragma unroll
    for (int t = 0; t < 10; t++) {
        float a = bkv[t];
        #pragma unroll
        for (int tp = 0; tp < 10; tp++) a = fmaf(xr[tp], w[tp * 10 + t], a);
        o[t] = a;
    }
    o[10] = 0.f; o[11] = 0.f;
}

// ---------------------------------------------------------------------------
// val = x @ Wv + bv  [640,1024]x[1024,1024]; stored TRANSPOSED [b][d][t pad12]
// 64x128 tile, register-prefetch pipeline. grid: (8, 10, 2)
// ---------------------------------------------------------------------------
__global__ __launch_bounds__(256) void k_val(const float* __restrict__ audio,
                                             const float* __restrict__ video,
                                             const float* __restrict__ Wv1,
                                             const float* __restrict__ bv1,
                                             const float* __restrict__ Wv2,
                                             const float* __restrict__ bv2) {
    const int br = blockIdx.z;
    const float* x  = br ? video : audio;
    const float* W  = br ? Wv2 : Wv1;
    const float* bv = br ? bv2 : bv1;

    __shared__ __align__(16) u64   sA[64][17];
    __shared__ __align__(16) float sB[16][132];
    const int bm = blockIdx.y * 64, bn = blockIdx.x * 128;
    const int tid = threadIdx.x;
    const int tx = tid & 15, ty = tid >> 4;
    const int ar = tid >> 2, ac4 = (tid & 3) * 4;
    const int br0 = tid >> 5, bc0 = (tid & 31) * 4;
    const int br1 = (tid + 256) >> 5, bc1 = bc0;

    float4 ra, rb0, rb1;
    ra  = *(const float4*)&x[(size_t)(bm + ar) * D_ + ac4];
    rb0 = *(const float4*)&W[(size_t)br0 * D_ + bn + bc0];
    rb1 = *(const float4*)&W[(size_t)br1 * D_ + bn + bc1];

    u64 acc[4][4] = {};
    for (int k0 = 0; k0 < D_; k0 += 16) {
        sA[ar][ac4 + 0] = pack2(ra.x, ra.x);
        sA[ar][ac4 + 1] = pack2(ra.y, ra.y);
        sA[ar][ac4 + 2] = pack2(ra.z, ra.z);
        sA[ar][ac4 + 3] = pack2(ra.w, ra.w);
        *(float4*)&sB[br0][bc0] = rb0;
        *(float4*)&sB[br1][bc1] = rb1;
        __syncthreads();

        int kn = k0 + 16;
        if (kn < D_) {
            ra  = *(const float4*)&x[(size_t)(bm + ar) * D_ + kn + ac4];
            rb0 = *(const float4*)&W[(size_t)(kn + br0) * D_ + bn + bc0];
            rb1 = *(const float4*)&W[(size_t)(kn + br1) * D_ + bn + bc1];
        }

        #pragma unroll
        for (int k = 0; k < 16; k++) {
            ulonglong2 bp0 = *(const ulonglong2*)&sB[k][tx * 8];
            ulonglong2 bp1 = *(const ulonglong2*)&sB[k][tx * 8 + 4];
            #pragma unroll
            for (int i = 0; i < 4; i++) {
                u64 ap = sA[ty * 4 + i][k];
                acc[i][0] = fma2(ap, bp0.x, acc[i][0]);
                acc[i][1] = fma2(ap, bp0.y, acc[i][1]);
                acc[i][2] = fma2(ap, bp1.x, acc[i][2]);
                acc[i][3] = fma2(ap, bp1.y, acc[i][3]);
            }
        }
        __syncthreads();
    }
    #pragma unroll
    for (int i = 0; i < 4; i++) {
        int m = bm + ty * 4 + i;
        int b = m / T_, t = m % T_;
        float c[8];
        unpack2(acc[i][0], c[0], c[1]);
        unpack2(acc[i][1], c[2], c[3]);
        unpack2(acc[i][2], c[4], c[5]);
        unpack2(acc[i][3], c[6], c[7]);
        #pragma unroll
        for (int j = 0; j < 8; j++) {
            int n = bn + tx * 8 + j;
            g_valT[br][(size_t)(b * D_ + n) * 12 + t] = c[j] + bv[n];
        }
    }
}

// ---------------------------------------------------------------------------
// Fused attention, ILP-restructured:
//   acc[t,e] = sum_d V[t,d] * tanh(SCALE * K[d,:] . J[:,e])
// Per d: score dot split into 2 independent 5-deep f32x2 chains + add;
// d processed in pairs -> 4 tanh batched; K-phase and V-phase separated.
// grid: (8 e-tiles, 64 b, 2 br)  block: 128 (2 e-cols/thread)
// ---------------------------------------------------------------------------
__global__ __launch_bounds__(128) void k_attn() {
    const int tid = threadIdx.x;
    const int e0  = blockIdx.x * 256 + tid * 2;
    const int b   = blockIdx.y;
    const int br  = blockIdx.z;

    __shared__ __align__(16) u64 sK[128][12];
    __shared__ __align__(16) u64 sV[128][12];

    const float* keyT = g_keyT[br] + (size_t)b * D_ * 12;
    const float* valT = g_valT[br] + (size_t)b * D_ * 12;
    const float* jp   = g_joint + (size_t)b * T_ * E_ + e0;

    u64 J[10], acc[10];
    #pragma unroll
    for (int t = 0; t < 10; t++) {
        float2 jv = *(const float2*)(jp + (size_t)t * E_);
        J[t]   = pack2(jv.x * SCALE_, jv.y * SCALE_);
        acc[t] = 0ull;
    }

    for (int d0 = 0; d0 < D_; d0 += 128) {
        __syncthreads();
        {
            const float4* kp = (const float4*)(keyT + (size_t)(d0 + tid) * 12);
            const float4* vp = (const float4*)(valT + (size_t)(d0 + tid) * 12);
            float4 ka = kp[0], kb4 = kp[1], kc = kp[2];
            float4 va = vp[0], vb4 = vp[1], vc = vp[2];
            u64* kd = sK[tid];
            u64* vd = sV[tid];
            kd[0] = pack2(ka.x, ka.x);   kd[1] = pack2(ka.y, ka.y);
            kd[2] = pack2(ka.z, ka.z);   kd[3] = pack2(ka.w, ka.w);
            kd[4] = pack2(kb4.x, kb4.x); kd[5] = pack2(kb4.y, kb4.y);
            kd[6] = pack2(kb4.z, kb4.z); kd[7] = pack2(kb4.w, kb4.w);
            kd[8] = pack2(kc.x, kc.x);   kd[9] = pack2(kc.y, kc.y);
            vd[0] = pack2(va.x, va.x);   vd[1] = pack2(va.y, va.y);
            vd[2] = pack2(va.z, va.z);   vd[3] = pack2(va.w, va.w);
            vd[4] = pack2(vb4.x, vb4.x); vd[5] = pack2(vb4.y, vb4.y);
            vd[6] = pack2(vb4.z, vb4.z); vd[7] = pack2(vb4.w, vb4.w);
            vd[8] = pack2(vc.x, vc.x);   vd[9] = pack2(vc.y, vc.y);
        }
        __syncthreads();

        #pragma unroll 2
        for (int dd = 0; dd < 128; dd += 2) {
            // --- score phase: two d rows, each as two 5-deep chains ---
            const ulonglong2* krA = (const ulonglong2*)sK[dd];
            const ulonglong2* krB = (const ulonglong2*)sK[dd + 1];
            ulonglong2 a01 = krA[0], a23 = krA[1], a45 = krA[2], a67 = krA[3], a89 = krA[4];
            ulonglong2 b01 = krB[0], b23 = krB[1], b45 = krB[2], b67 = krB[3], b89 = krB[4];

            u64 paL = mul2(a01.x, J[0]);
            u64 paH = mul2(a01.y, J[1]);
            u64 pbL = mul2(b01.x, J[0]);
            u64 pbH = mul2(b01.y, J[1]);
            paL = fma2(a23.x, J[2], paL);  paH = fma2(a23.y, J[3], paH);
            pbL = fma2(b23.x, J[2], pbL);  pbH = fma2(b23.y, J[3], pbH);
            paL = fma2(a45.x, J[4], paL);  paH = fma2(a45.y, J[5], paH);
            pbL = fma2(b45.x, J[4], pbL);  pbH = fma2(b45.y, J[5], pbH);
            paL = fma2(a67.x, J[6], paL);  paH = fma2(a67.y, J[7], paH);
            pbL = fma2(b67.x, J[6], pbL);  pbH = fma2(b67.y, J[7], pbH);
            paL = fma2(a89.x, J[8], paL);  paH = fma2(a89.y, J[9], paH);
            pbL = fma2(b89.x, J[8], pbL);  pbH = fma2(b89.y, J[9], pbH);
            u64 pa = add2(paL, paH);
            u64 pb = add2(pbL, pbH);

            // --- tanh phase (4 MUFU batched) ---
            float pa0, pa1, pb0, pb1;
            unpack2(pa, pa0, pa1);
            unpack2(pb, pb0, pb1);
            u64 sa = pack2(tanh_fast(pa0), tanh_fast(pa1));
            u64 sb = pack2(tanh_fast(pb0), tanh_fast(pb1));

            // --- accumulate phase ---
            const ulonglong2* vrA = (const ulonglong2*)sV[dd];
            const ulonglong2* vrB = (const ulonglong2*)sV[dd + 1];
            ulonglong2 va01 = vrA[0], va23 = vrA[1], va45 = vrA[2], va67 = vrA[3], va89 = vrA[4];
            ulonglong2 vb01 = vrB[0], vb23 = vrB[1], vb45 = vrB[2], vb67 = vrB[3], vb89 = vrB[4];
            acc[0] = fma2(va01.x, sa, acc[0]);
            acc[1] = fma2(va01.y, sa, acc[1]);
            acc[2] = fma2(va23.x, sa, acc[2]);
            acc[3] = fma2(va23.y, sa, acc[3]);
            acc[4] = fma2(va45.x, sa, acc[4]);
            acc[5] = fma2(va45.y, sa, acc[5]);
            acc[6] = fma2(va67.x, sa, acc[6]);
            acc[7] = fma2(va67.y, sa, acc[7]);
            acc[8] = fma2(va89.x, sa, acc[8]);
            acc[9] = fma2(va89.y, sa, acc[9]);
            acc[0] = fma2(vb01.x, sb, acc[0]);
            acc[1] = fma2(vb01.y, sb, acc[1]);
            acc[2] = fma2(vb23.x, sb, acc[2]);
            acc[3] = fma2(vb23.y, sb, acc[3]);
            acc[4] = fma2(vb45.x, sb, acc[4]);
            acc[5] = fma2(vb45.y, sb, acc[5]);
            acc[6] = fma2(vb67.x, sb, acc[6]);
            acc[7] = fma2(vb67.y, sb, acc[7]);
            acc[8] = fma2(vb89.x, sb, acc[8]);
            acc[9] = fma2(vb89.y, sb, acc[9]);
        }
    }

    float* o = g_att[br] + (size_t)b * T_ * E_ + e0;
    #pragma unroll
    for (int t = 0; t < 10; t++) {
        float x0, x1;
        unpack2(acc[t], x0, x1);
        float2 r;
        r.x = fmaxf(tanhf(x0), 0.f);
        r.y = fmaxf(tanhf(x1), 0.f);
        *(float2*)(o + (size_t)t * E_) = r;
    }
}

// ---------------------------------------------------------------------------
// out = audio + video + relu(att0 @ Wf + bf) + relu(att1 @ Wf + bf)
// 32x128 tile, register-prefetch pipeline, shared W tiles.
// grid: (8, 20)  block: 256
// ---------------------------------------------------------------------------
__global__ __launch_bounds__(256) void k_fuse(const float* __restrict__ audio,
                                              const float* __restrict__ video,
                                              const float* __restrict__ Wf,
                                              const float* __restrict__ bf,
                                              float* __restrict__ out) {
    __shared__ __align__(16) u64   sA0[32][17];
    __shared__ __align__(16) u64   sA1[32][17];
    __shared__ __align__(16) float sB[16][132];
    const int bm = blockIdx.y * 32, bn = blockIdx.x * 128;
    const int tid = threadIdx.x;
    const int tx = tid & 15, ty = tid >> 4;
    const int ar = tid >> 3, ac2 = (tid & 7) * 2;           // A: 32x16, float2/thread
    const int br0 = tid >> 5, bc0 = (tid & 31) * 4;
    const int br1 = (tid + 256) >> 5, bc1 = bc0;

    float2 ra0, ra1;
    float4 rb0, rb1;
    ra0 = *(const float2*)&g_att[0][(size_t)(bm + ar) * E_ + ac2];
    ra1 = *(const float2*)&g_att[1][(size_t)(bm + ar) * E_ + ac2];
    rb0 = *(const float4*)&Wf[(size_t)br0 * D_ + bn + bc0];
    rb1 = *(const float4*)&Wf[(size_t)br1 * D_ + bn + bc1];

    u64 acc0[2][4] = {}, acc1[2][4] = {};
    for (int k0 = 0; k0 < E_; k0 += 16) {
        sA0[ar][ac2 + 0] = pack2(ra0.x, ra0.x);
        sA0[ar][ac2 + 1] = pack2(ra0.y, ra0.y);
        sA1[ar][ac2 + 0] = pack2(ra1.x, ra1.x);
        sA1[ar][ac2 + 1] = pack2(ra1.y, ra1.y);
        *(float4*)&sB[br0][bc0] = rb0;
        *(float4*)&sB[br1][bc1] = rb1;
        __syncthreads();

        int kn = k0 + 16;
        if (kn < E_) {
            ra0 = *(const float2*)&g_att[0][(size_t)(bm + ar) * E_ + kn + ac2];
            ra1 = *(const float2*)&g_att[1][(size_t)(bm + ar) * E_ + kn + ac2];
            rb0 = *(const float4*)&Wf[(size_t)(kn + br0) * D_ + bn + bc0];
            rb1 = *(const float4*)&Wf[(size_t)(kn + br1) * D_ + bn + bc1];
        }

        #pragma unroll
        for (int k = 0; k < 16; k++) {
            ulonglong2 bp0 = *(const ulonglong2*)&sB[k][tx * 8];
            ulonglong2 bp1 = *(const ulonglong2*)&sB[k][tx * 8 + 4];
            #pragma unroll
            for (int i = 0; i < 2; i++) {
                u64 a0 = sA0[ty * 2 + i][k];
                u64 a1 = sA1[ty * 2 + i][k];
                acc0[i][0] = fma2(a0, bp0.x, acc0[i][0]);
                acc0[i][1] = fma2(a0, bp0.y, acc0[i][1]);
                acc0[i][2] = fma2(a0, bp1.x, acc0[i][2]);
                acc0[i][3] = fma2(a0, bp1.y, acc0[i][3]);
                acc1[i][0] = fma2(a1, bp0.x, acc1[i][0]);
                acc1[i][1] = fma2(a1, bp0.y, acc1[i][1]);
                acc1[i][2] = fma2(a1, bp1.x, acc1[i][2]);
                acc1[i][3] = fma2(a1, bp1.y, acc1[i][3]);
            }
        }
        __syncthreads();
    }
    float4 bias0 = *(const float4*)&bf[bn + tx * 8];
    float4 bias1 = *(const float4*)&bf[bn + tx * 8 + 4];
    #pragma unroll
    for (int i = 0; i < 2; i++) {
        int m = bm + ty * 2 + i;
        float c0[8], c1[8];
        unpack2(acc0[i][0], c0[0], c0[1]);
        unpack2(acc0[i][1], c0[2], c0[3]);
        unpack2(acc0[i][2], c0[4], c0[5]);
        unpack2(acc0[i][3], c0[6], c0[7]);
        unpack2(acc1[i][0], c1[0], c1[1]);
        unpack2(acc1[i][1], c1[2], c1[3]);
        unpack2(acc1[i][2], c1[4], c1[5]);
        unpack2(acc1[i][3], c1[6], c1[7]);
        const float* ap = &audio[(size_t)m * D_ + bn + tx * 8];
        const float* vp = &video[(size_t)m * D_ + bn + tx * 8];
        float4 av0 = *(const float4*)ap, av1 = *(const float4*)(ap + 4);
        float4 vv0 = *(const float4*)vp, vv1 = *(const float4*)(vp + 4);
        float4 o0, o1;
        o0.x = av0.x + vv0.x + fmaxf(c0[0] + bias0.x, 0.f) + fmaxf(c1[0] + bias0.x, 0.f);
        o0.y = av0.y + vv0.y + fmaxf(c0[1] + bias0.y, 0.f) + fmaxf(c1[1] + bias0.y, 0.f);
        o0.z = av0.z + vv0.z + fmaxf(c0[2] + bias0.z, 0.f) + fmaxf(c1[2] + bias0.z, 0.f);
        o0.w = av0.w + vv0.w + fmaxf(c0[3] + bias0.w, 0.f) + fmaxf(c1[3] + bias0.w, 0.f);
        o1.x = av1.x + vv1.x + fmaxf(c0[4] + bias1.x, 0.f) + fmaxf(c1[4] + bias1.x, 0.f);
        o1.y = av1.y + vv1.y + fmaxf(c0[5] + bias1.y, 0.f) + fmaxf(c1[5] + bias1.y, 0.f);
        o1.z = av1.z + vv1.z + fmaxf(c0[6] + bias1.z, 0.f) + fmaxf(c1[6] + bias1.z, 0.f);
        o1.w = av1.w + vv1.w + fmaxf(c0[7] + bias1.w, 0.f) + fmaxf(c1[7] + bias1.w, 0.f);
        float* dst = &out[(size_t)m * D_ + bn + tx * 8];
        *(float4*)dst = o0;
        *(float4*)(dst + 4) = o1;
    }
}

// ---------------------------------------------------------------------------
// Launch
// ---------------------------------------------------------------------------
extern "C" void kernel_launch(void* const* d_in, const int* in_sizes, int n_in,
                              void* d_out, int out_size) {
    (void)in_sizes; (void)n_in; (void)out_size;
    const float* audio = (const float*)d_in[0];
    const float* video = (const float*)d_in[1];
    const float* Wq  = (const float*)d_in[2];
    const float* bq  = (const float*)d_in[3];
    const float* Wk1 = (const float*)d_in[4];
    const float* bk1 = (const float*)d_in[5];
    const float* Wk2 = (const float*)d_in[6];
    const float* bk2 = (const float*)d_in[7];
    const float* Wv1 = (const float*)d_in[8];
    const float* bv1 = (const float*)d_in[9];
    const float* Wv2 = (const float*)d_in[10];
    const float* bv2 = (const float*)d_in[11];
    const float* Wf  = (const float*)d_in[12];
    const float* bf  = (const float*)d_in[13];
    float* out = (float*)d_out;

    k_joint<<<dim3(16, 10), 256>>>(audio, video, Wq, bq);
    k_key<<<dim3(256, 2), 256>>>(audio, video, Wk1, bk1, Wk2, bk2);
    k_val<<<dim3(8, 10, 2), 256>>>(audio, video, Wv1, bv1, Wv2, bv2);
    k_attn<<<dim3(8, 64, 2), 128>>>();
    k_fuse<<<dim3(8, 20), 256>>>(audio, video, Wf, bf, out);
}